// round 5
// baseline (speedup 1.0000x reference)
#include <cuda_runtime.h>

#define D 128
#define NMAX 50048
#define EMAX 1000000

// Scratch (__device__ globals — allocation-free rule)
__device__ float g_h[NMAX * D];      // h' = dis[r] * (x @ W^T + b)[r]
__device__ float g_dis[NMAX];        // (deg+1)^-0.5
__device__ int   g_degi[NMAX];       // edge count per source
__device__ int   g_cnt[NMAX];        // edge count per target
__device__ int   g_off[NMAX + 1];    // CSR offsets (by target)
__device__ int   g_cur[NMAX];        // fill cursors
__device__ int   g_src[EMAX];        // CSR payload: source index per edge

// ---------------------------------------------------------------------------
__global__ void k_zero(int n) {
    int i = blockIdx.x * blockDim.x + threadIdx.x;
    if (i < n) { g_degi[i] = 0; g_cnt[i] = 0; }
}

__global__ void k_count(const int* __restrict__ ei, int E) {
    int e = blockIdx.x * blockDim.x + threadIdx.x;
    if (e >= E) return;
    atomicAdd(&g_degi[ei[e]], 1);      // source (deg for norm)
    atomicAdd(&g_cnt[ei[E + e]], 1);   // target (CSR)
}

// single-block exclusive scan of g_cnt -> g_off/g_cur, plus dis = rsqrt(deg+1)
__global__ void k_scan(int n) {
    __shared__ int sums[1024];
    int t = threadIdx.x;
    int chunk = (n + 1023) >> 10;
    int lo = t * chunk, hi = min(lo + chunk, n);
    int s = 0;
    for (int i = lo; i < hi; i++) {
        s += g_cnt[i];
        g_dis[i] = rsqrtf((float)(g_degi[i] + 1));  // fused k_dis
    }
    sums[t] = s;
    __syncthreads();
    for (int off = 1; off < 1024; off <<= 1) {
        int v = (t >= off) ? sums[t - off] : 0;
        __syncthreads();
        sums[t] += v;
        __syncthreads();
    }
    int base = (t == 0) ? 0 : sums[t - 1];
    for (int i = lo; i < hi; i++) {
        g_off[i] = base;
        g_cur[i] = base;
        base += g_cnt[i];
    }
    if (t == 1023) g_off[n] = base;
}

__global__ void k_fill(const int* __restrict__ ei, int E) {
    int e = blockIdx.x * blockDim.x + threadIdx.x;
    if (e >= E) return;
    int r = ei[e];
    int c = ei[E + e];
    int pos = atomicAdd(&g_cur[c], 1);
    g_src[pos] = r;
}

// ---------------------------------------------------------------------------
// GEMM: g_h[r][c] = dis[r] * (sum_k x[r][k]*W[c][k] + b[c])
// 128x128 tile per 256-thread block; 8x8 outputs per thread.
// Ws[k][c] fully staged (64KB). xs stored k-major per 16-k chunk, double buffered.
#define XCHUNK 16
#define XBUF (XCHUNK * 128)   // 2048 floats per buffer

__global__ __launch_bounds__(256, 2)
void k_gemm(const float* __restrict__ x, const float* __restrict__ W,
            const float* __restrict__ b, int n) {
    extern __shared__ float sm[];
    float* Ws = sm;                 // [128][128] : Ws[k][c] = W[c][k]
    float* xs = sm + D * D;         // [2][XCHUNK][128] : xs[buf][kl][row]

    int t  = threadIdx.x;
    int tx = t & 15;                // 16 col-groups
    int ty = t >> 4;                // 16 row-groups
    int row0 = blockIdx.x * 128;

    // Load W transposed into Ws[k][c] (conflict-free STS)
    for (int i = t; i < (D * D) / 4; i += 256) {
        int c  = i & 127;
        int k4 = (i >> 7) << 2;
        float4 w = *(const float4*)&W[c * D + k4];
        Ws[(k4 + 0) * D + c] = w.x;
        Ws[(k4 + 1) * D + c] = w.y;
        Ws[(k4 + 2) * D + c] = w.z;
        Ws[(k4 + 3) * D + c] = w.w;
    }

    // Prologue: stage chunk 0 (k-major)
    {
        int j0 = t * 2;
#pragma unroll
        for (int u = 0; u < 2; u++) {
            int j = j0 + u;
            int r = j >> 2;
            int kk = (j & 3) * 4;
            int row = row0 + r;
            float4 v = make_float4(0.f, 0.f, 0.f, 0.f);
            if (row < n) v = *(const float4*)&x[row * D + kk];
            xs[(kk + 0) * 128 + r] = v.x;
            xs[(kk + 1) * 128 + r] = v.y;
            xs[(kk + 2) * 128 + r] = v.z;
            xs[(kk + 3) * 128 + r] = v.w;
        }
    }
    __syncthreads();

    float acc[8][8];
#pragma unroll
    for (int i = 0; i < 8; i++)
#pragma unroll
        for (int j = 0; j < 8; j++) acc[i][j] = 0.f;

    for (int c = 0; c < D / XCHUNK; c++) {
        // Prefetch next chunk into registers
        float4 p[2];
        if (c < D / XCHUNK - 1) {
            int k0 = (c + 1) * XCHUNK;
            int j0 = t * 2;
#pragma unroll
            for (int u = 0; u < 2; u++) {
                int j = j0 + u;
                int r = j >> 2;
                int kk = (j & 3) * 4;
                int row = row0 + r;
                p[u] = make_float4(0.f, 0.f, 0.f, 0.f);
                if (row < n) p[u] = *(const float4*)&x[row * D + k0 + kk];
            }
        }

        const float* xb = &xs[(c & 1) * XBUF];
#pragma unroll
        for (int kl = 0; kl < XCHUNK; kl++) {
            const float* wrow = &Ws[(c * XCHUNK + kl) * D];
            float4 b0 = *(const float4*)&wrow[tx * 4];
            float4 b1 = *(const float4*)&wrow[64 + tx * 4];
            float rA[8];
#pragma unroll
            for (int i = 0; i < 8; i++) rA[i] = xb[kl * 128 + ty * 8 + i];
#pragma unroll
            for (int i = 0; i < 8; i++) {
                acc[i][0] += rA[i] * b0.x;
                acc[i][1] += rA[i] * b0.y;
                acc[i][2] += rA[i] * b0.z;
                acc[i][3] += rA[i] * b0.w;
                acc[i][4] += rA[i] * b1.x;
                acc[i][5] += rA[i] * b1.y;
                acc[i][6] += rA[i] * b1.z;
                acc[i][7] += rA[i] * b1.w;
            }
        }

        if (c < D / XCHUNK - 1) {
            float* dst = &xs[((c + 1) & 1) * XBUF];
            int j0 = t * 2;
#pragma unroll
            for (int u = 0; u < 2; u++) {
                int j = j0 + u;
                int r = j >> 2;
                int kk = (j & 3) * 4;
                dst[(kk + 0) * 128 + r] = p[u].x;
                dst[(kk + 1) * 128 + r] = p[u].y;
                dst[(kk + 2) * 128 + r] = p[u].z;
                dst[(kk + 3) * 128 + r] = p[u].w;
            }
        }
        __syncthreads();
    }

    // Epilogue: += bias, * dis[row], store
    float4 bv0 = *(const float4*)&b[tx * 4];
    float4 bv1 = *(const float4*)&b[64 + tx * 4];
#pragma unroll
    for (int i = 0; i < 8; i++) {
        int row = row0 + ty * 8 + i;
        if (row >= n) break;
        float dv = g_dis[row];
        float4 o0, o1;
        o0.x = (acc[i][0] + bv0.x) * dv;
        o0.y = (acc[i][1] + bv0.y) * dv;
        o0.z = (acc[i][2] + bv0.z) * dv;
        o0.w = (acc[i][3] + bv0.w) * dv;
        o1.x = (acc[i][4] + bv1.x) * dv;
        o1.y = (acc[i][5] + bv1.y) * dv;
        o1.z = (acc[i][6] + bv1.z) * dv;
        o1.w = (acc[i][7] + bv1.w) * dv;
        *(float4*)&g_h[row * D + tx * 4] = o0;
        *(float4*)&g_h[row * D + 64 + tx * 4] = o1;
    }
}

// ---------------------------------------------------------------------------
// Fused gather + self-loop + ReLU + LayerNorm + residual. Warp per node.
// Plain serial gather loop (R3 version — measured fastest; unrolled variant
// regressed via L1tex queue overflow).
__global__ void k_agg(const float* __restrict__ x,
                      const float* __restrict__ gamma,
                      const float* __restrict__ beta,
                      float* __restrict__ out, int n) {
    int node = (blockIdx.x * blockDim.x + threadIdx.x) >> 5;
    int lane = threadIdx.x & 31;
    if (node >= n) return;

    float dc = g_dis[node];
    int lo = g_off[node], hi = g_off[node + 1];
    int l4 = lane * 4;

    float4 acc = make_float4(0.f, 0.f, 0.f, 0.f);
    for (int i = lo; i < hi; i++) {
        int r = g_src[i];  // lane-uniform (warp-broadcast load)
        float4 m = *(const float4*)&g_h[r * D + l4];
        acc.x += m.x; acc.y += m.y; acc.z += m.z; acc.w += m.w;
    }
    // self loop
    float4 hs = *(const float4*)&g_h[node * D + l4];
    acc.x += hs.x; acc.y += hs.y; acc.z += hs.z; acc.w += hs.w;

    float4 v;
    v.x = fmaxf(acc.x * dc, 0.f);
    v.y = fmaxf(acc.y * dc, 0.f);
    v.z = fmaxf(acc.z * dc, 0.f);
    v.w = fmaxf(acc.w * dc, 0.f);

    float s  = v.x + v.y + v.z + v.w;
    float ss = v.x * v.x + v.y * v.y + v.z * v.z + v.w * v.w;
#pragma unroll
    for (int o = 16; o; o >>= 1) {
        s  += __shfl_xor_sync(0xffffffffu, s,  o);
        ss += __shfl_xor_sync(0xffffffffu, ss, o);
    }
    float mu  = s * (1.f / 128.f);
    float var = ss * (1.f / 128.f) - mu * mu;
    float inv = rsqrtf(var + 1e-5f);

    float4 g  = *(const float4*)&gamma[l4];
    float4 be = *(const float4*)&beta[l4];
    float4 xv = *(const float4*)&x[node * D + l4];

    float4 o;
    o.x = (v.x - mu) * inv * g.x + be.x + xv.x;
    o.y = (v.y - mu) * inv * g.y + be.y + xv.y;
    o.z = (v.z - mu) * inv * g.z + be.z + xv.z;
    o.w = (v.w - mu) * inv * g.w + be.w + xv.w;
    *(float4*)&out[node * D + l4] = o;
}

// ---------------------------------------------------------------------------
extern "C" void kernel_launch(void* const* d_in, const int* in_sizes, int n_in,
                              void* d_out, int out_size) {
    const float* x     = (const float*)d_in[0];
    const int*   ei    = (const int*)d_in[1];    // int32 (JAX x64 disabled)
    const float* W     = (const float*)d_in[2];
    const float* b     = (const float*)d_in[3];
    const float* gamma = (const float*)d_in[4];
    const float* beta  = (const float*)d_in[5];
    float*       out   = (float*)d_out;

    int n = in_sizes[0] / D;
    int E = in_sizes[1] / 2;

    k_zero<<<(n + 255) / 256, 256>>>(n);
    k_count<<<(E + 255) / 256, 256>>>(ei, E);
    k_scan<<<1, 1024>>>(n);          // also computes g_dis

    k_fill<<<(E + 255) / 256, 256>>>(ei, E);

    int smem = (D * D + 2 * XBUF) * sizeof(float);  // 80 KB
    cudaFuncSetAttribute(k_gemm, cudaFuncAttributeMaxDynamicSharedMemorySize, smem);
    k_gemm<<<(n + 127) / 128, 256, smem>>>(x, W, b, n);

    k_agg<<<(n + 7) / 8, 256>>>(x, gamma, beta, out, n);
}

// round 6
// speedup vs baseline: 1.2732x; 1.2732x over previous
#include <cuda_runtime.h>

#define D 128
#define NMAX 50048
#define EMAX 1000000

// Scratch (__device__ globals — allocation-free rule)
__device__ float g_h[NMAX * D];      // h' = dis[r] * (x @ W^T + b)[r]
__device__ float g_dis[NMAX];        // (deg+1)^-0.5
__device__ int   g_degi[NMAX];       // edge count per source
__device__ int   g_cnt[NMAX];        // edge count per target
__device__ int   g_off[NMAX + 1];    // CSR offsets (by target)
__device__ int   g_cur[NMAX];        // fill cursors
__device__ int   g_src[EMAX];        // CSR payload: source index per edge

// ---------------------------------------------------------------------------
__global__ void k_zero(int n) {
    int i = blockIdx.x * blockDim.x + threadIdx.x;
    if (i < n) { g_degi[i] = 0; g_cnt[i] = 0; }
}

// histogram both endpoints (edge_index is int32)
__global__ void k_count(const int* __restrict__ ei, int E) {
    int e = blockIdx.x * blockDim.x + threadIdx.x;
    if (e >= E) return;
    atomicAdd(&g_degi[ei[e]], 1);      // source (deg for norm)
    atomicAdd(&g_cnt[ei[E + e]], 1);   // target (CSR)
}

__global__ void k_dis(int n) {
    int i = blockIdx.x * blockDim.x + threadIdx.x;
    if (i < n) g_dis[i] = rsqrtf((float)(g_degi[i] + 1));  // +1 self loop
}

// single-block exclusive scan of g_cnt -> g_off, g_cur  (R3 version, unfused)
__global__ void k_scan(int n) {
    __shared__ int sums[1024];
    int t = threadIdx.x;
    int chunk = (n + 1023) >> 10;
    int lo = t * chunk, hi = min(lo + chunk, n);
    int s = 0;
    for (int i = lo; i < hi; i++) s += g_cnt[i];
    sums[t] = s;
    __syncthreads();
    for (int off = 1; off < 1024; off <<= 1) {
        int v = (t >= off) ? sums[t - off] : 0;
        __syncthreads();
        sums[t] += v;
        __syncthreads();
    }
    int base = (t == 0) ? 0 : sums[t - 1];
    for (int i = lo; i < hi; i++) {
        g_off[i] = base;
        g_cur[i] = base;
        base += g_cnt[i];
    }
    if (t == 1023) g_off[n] = base;
}

// bin edges into CSR by target
__global__ void k_fill(const int* __restrict__ ei, int E) {
    int e = blockIdx.x * blockDim.x + threadIdx.x;
    if (e >= E) return;
    int r = ei[e];
    int c = ei[E + e];
    int pos = atomicAdd(&g_cur[c], 1);
    g_src[pos] = r;
}

// ---------------------------------------------------------------------------
// GEMM (R4 register-tiled version, ncu-measured 52.2us):
// g_h[r][c] = dis[r] * (sum_k x[r][k]*W[c][k] + b[c])
// 128x128 tile per 256-thread block; 8x8 outputs per thread.
#define XCHUNK 16
#define XBUF (XCHUNK * 128)   // 2048 floats per buffer

__global__ __launch_bounds__(256, 2)
void k_gemm(const float* __restrict__ x, const float* __restrict__ W,
            const float* __restrict__ b, int n) {
    extern __shared__ float sm[];
    float* Ws = sm;                 // [128][128] : Ws[k][c] = W[c][k]
    float* xs = sm + D * D;         // [2][XCHUNK][128] : xs[buf][kl][row]

    int t  = threadIdx.x;
    int tx = t & 15;                // 16 col-groups
    int ty = t >> 4;                // 16 row-groups
    int row0 = blockIdx.x * 128;

    // Load W transposed into Ws[k][c] (conflict-free STS)
    for (int i = t; i < (D * D) / 4; i += 256) {
        int c  = i & 127;
        int k4 = (i >> 7) << 2;
        float4 w = *(const float4*)&W[c * D + k4];
        Ws[(k4 + 0) * D + c] = w.x;
        Ws[(k4 + 1) * D + c] = w.y;
        Ws[(k4 + 2) * D + c] = w.z;
        Ws[(k4 + 3) * D + c] = w.w;
    }

    // Prologue: stage chunk 0 (k-major)
    {
        int j0 = t * 2;
#pragma unroll
        for (int u = 0; u < 2; u++) {
            int j = j0 + u;
            int r = j >> 2;
            int kk = (j & 3) * 4;
            int row = row0 + r;
            float4 v = make_float4(0.f, 0.f, 0.f, 0.f);
            if (row < n) v = *(const float4*)&x[row * D + kk];
            xs[(kk + 0) * 128 + r] = v.x;
            xs[(kk + 1) * 128 + r] = v.y;
            xs[(kk + 2) * 128 + r] = v.z;
            xs[(kk + 3) * 128 + r] = v.w;
        }
    }
    __syncthreads();

    float acc[8][8];
#pragma unroll
    for (int i = 0; i < 8; i++)
#pragma unroll
        for (int j = 0; j < 8; j++) acc[i][j] = 0.f;

    for (int c = 0; c < D / XCHUNK; c++) {
        float4 p[2];
        if (c < D / XCHUNK - 1) {
            int k0 = (c + 1) * XCHUNK;
            int j0 = t * 2;
#pragma unroll
            for (int u = 0; u < 2; u++) {
                int j = j0 + u;
                int r = j >> 2;
                int kk = (j & 3) * 4;
                int row = row0 + r;
                p[u] = make_float4(0.f, 0.f, 0.f, 0.f);
                if (row < n) p[u] = *(const float4*)&x[row * D + k0 + kk];
            }
        }

        const float* xb = &xs[(c & 1) * XBUF];
#pragma unroll
        for (int kl = 0; kl < XCHUNK; kl++) {
            const float* wrow = &Ws[(c * XCHUNK + kl) * D];
            float4 b0 = *(const float4*)&wrow[tx * 4];
            float4 b1 = *(const float4*)&wrow[64 + tx * 4];
            float rA[8];
#pragma unroll
            for (int i = 0; i < 8; i++) rA[i] = xb[kl * 128 + ty * 8 + i];
#pragma unroll
            for (int i = 0; i < 8; i++) {
                acc[i][0] += rA[i] * b0.x;
                acc[i][1] += rA[i] * b0.y;
                acc[i][2] += rA[i] * b0.z;
                acc[i][3] += rA[i] * b0.w;
                acc[i][4] += rA[i] * b1.x;
                acc[i][5] += rA[i] * b1.y;
                acc[i][6] += rA[i] * b1.z;
                acc[i][7] += rA[i] * b1.w;
            }
        }

        if (c < D / XCHUNK - 1) {
            float* dst = &xs[((c + 1) & 1) * XBUF];
            int j0 = t * 2;
#pragma unroll
            for (int u = 0; u < 2; u++) {
                int j = j0 + u;
                int r = j >> 2;
                int kk = (j & 3) * 4;
                dst[(kk + 0) * 128 + r] = p[u].x;
                dst[(kk + 1) * 128 + r] = p[u].y;
                dst[(kk + 2) * 128 + r] = p[u].z;
                dst[(kk + 3) * 128 + r] = p[u].w;
            }
        }
        __syncthreads();
    }

    // Epilogue: += bias, * dis[row], store
    float4 bv0 = *(const float4*)&b[tx * 4];
    float4 bv1 = *(const float4*)&b[64 + tx * 4];
#pragma unroll
    for (int i = 0; i < 8; i++) {
        int row = row0 + ty * 8 + i;
        if (row >= n) break;
        float dv = g_dis[row];
        float4 o0, o1;
        o0.x = (acc[i][0] + bv0.x) * dv;
        o0.y = (acc[i][1] + bv0.y) * dv;
        o0.z = (acc[i][2] + bv0.z) * dv;
        o0.w = (acc[i][3] + bv0.w) * dv;
        o1.x = (acc[i][4] + bv1.x) * dv;
        o1.y = (acc[i][5] + bv1.y) * dv;
        o1.z = (acc[i][6] + bv1.z) * dv;
        o1.w = (acc[i][7] + bv1.w) * dv;
        *(float4*)&g_h[row * D + tx * 4] = o0;
        *(float4*)&g_h[row * D + 64 + tx * 4] = o1;
    }
}

// ---------------------------------------------------------------------------
// Fused gather + self-loop + ReLU + LayerNorm + residual. Warp per node.
// (exact R3 version)
__global__ void k_agg(const float* __restrict__ x,
                      const float* __restrict__ gamma,
                      const float* __restrict__ beta,
                      float* __restrict__ out, int n) {
    int node = (blockIdx.x * blockDim.x + threadIdx.x) >> 5;
    int lane = threadIdx.x & 31;
    if (node >= n) return;

    float dc = g_dis[node];
    int lo = g_off[node], hi = g_off[node + 1];

    float4 acc = make_float4(0.f, 0.f, 0.f, 0.f);
    for (int i = lo; i < hi; i++) {
        int r = g_src[i];  // lane-uniform (warp-broadcast load)
        float4 m = *(const float4*)&g_h[r * D + lane * 4];
        acc.x += m.x; acc.y += m.y; acc.z += m.z; acc.w += m.w;
    }
    // self loop
    float4 hs = *(const float4*)&g_h[node * D + lane * 4];
    acc.x += hs.x; acc.y += hs.y; acc.z += hs.z; acc.w += hs.w;

    float4 v;
    v.x = fmaxf(acc.x * dc, 0.f);
    v.y = fmaxf(acc.y * dc, 0.f);
    v.z = fmaxf(acc.z * dc, 0.f);
    v.w = fmaxf(acc.w * dc, 0.f);

    float s  = v.x + v.y + v.z + v.w;
    float ss = v.x * v.x + v.y * v.y + v.z * v.z + v.w * v.w;
#pragma unroll
    for (int o = 16; o; o >>= 1) {
        s  += __shfl_xor_sync(0xffffffffu, s,  o);
        ss += __shfl_xor_sync(0xffffffffu, ss, o);
    }
    float mu  = s * (1.f / 128.f);
    float var = ss * (1.f / 128.f) - mu * mu;
    float inv = rsqrtf(var + 1e-5f);

    float4 g  = *(const float4*)&gamma[lane * 4];
    float4 be = *(const float4*)&beta[lane * 4];
    float4 xv = *(const float4*)&x[node * D + lane * 4];

    float4 o;
    o.x = (v.x - mu) * inv * g.x + be.x + xv.x;
    o.y = (v.y - mu) * inv * g.y + be.y + xv.y;
    o.z = (v.z - mu) * inv * g.z + be.z + xv.z;
    o.w = (v.w - mu) * inv * g.w + be.w + xv.w;
    *(float4*)&out[node * D + lane * 4] = o;
}

// ---------------------------------------------------------------------------
extern "C" void kernel_launch(void* const* d_in, const int* in_sizes, int n_in,
                              void* d_out, int out_size) {
    const float* x     = (const float*)d_in[0];
    const int*   ei    = (const int*)d_in[1];    // int32 (JAX x64 disabled)
    const float* W     = (const float*)d_in[2];
    const float* b     = (const float*)d_in[3];
    const float* gamma = (const float*)d_in[4];
    const float* beta  = (const float*)d_in[5];
    float*       out   = (float*)d_out;

    int n = in_sizes[0] / D;
    int E = in_sizes[1] / 2;

    // R3 launch order, exactly.
    k_zero<<<(n + 255) / 256, 256>>>(n);
    k_count<<<(E + 255) / 256, 256>>>(ei, E);
    k_dis<<<(n + 255) / 256, 256>>>(n);

    int smem = (D * D + 2 * XBUF) * sizeof(float);  // 80 KB
    cudaFuncSetAttribute(k_gemm, cudaFuncAttributeMaxDynamicSharedMemorySize, smem);
    k_gemm<<<(n + 127) / 128, 256, smem>>>(x, W, b, n);

    k_scan<<<1, 1024>>>(n);
    k_fill<<<(E + 255) / 256, 256>>>(ei, E);

    k_agg<<<(n + 7) / 8, 256>>>(x, gamma, beta, out, n);
}

// round 7
// speedup vs baseline: 2.0525x; 1.6121x over previous
#include <cuda_runtime.h>

#define D 128
#define NMAX 50048
#define EMAX 1000000
#define SCAN_ELEMS 1024              // elements per scan block (256 thr x 4)
#define SCAN_MAXBLK 64

// Scratch (__device__ globals — allocation-free rule)
__device__ float g_h[NMAX * D];      // h' = dis[r] * (x @ W^T + b)[r]
__device__ float g_dis[NMAX];        // (deg+1)^-0.5
__device__ int   g_degi[NMAX];       // edge count per source
__device__ int   g_cnt[NMAX];        // edge count per target
__device__ int   g_off[NMAX + 1];    // CSR offsets (by target)
__device__ int   g_cur[NMAX];        // fill cursors
__device__ int   g_src[EMAX];        // CSR payload: source index per edge
__device__ int   g_bsum[SCAN_MAXBLK];  // scan phase-1 block partials
__device__ int   g_boff[SCAN_MAXBLK];  // scan phase-2 exclusive block offsets

// ---------------------------------------------------------------------------
__global__ void k_zero(int n) {
    int i = blockIdx.x * blockDim.x + threadIdx.x;
    if (i < n) { g_degi[i] = 0; g_cnt[i] = 0; }
}

// histogram both endpoints (edge_index is int32)
__global__ void k_count(const int* __restrict__ ei, int E) {
    int e = blockIdx.x * blockDim.x + threadIdx.x;
    if (e >= E) return;
    atomicAdd(&g_degi[ei[e]], 1);      // source (deg for norm)
    atomicAdd(&g_cnt[ei[E + e]], 1);   // target (CSR)
}

__global__ void k_dis(int n) {
    int i = blockIdx.x * blockDim.x + threadIdx.x;
    if (i < n) g_dis[i] = rsqrtf((float)(g_degi[i] + 1));  // +1 self loop
}

// --- parallel exclusive scan of g_cnt -> g_off, g_cur --------------------
// Phase 1: per-block (1024-element) sums
__global__ void k_scan1(int n) {
    __shared__ int wsum[8];
    int t = threadIdx.x;
    int base = blockIdx.x * SCAN_ELEMS + t * 4;
    int s = 0;
#pragma unroll
    for (int u = 0; u < 4; u++) {
        int i = base + u;
        if (i < n) s += g_cnt[i];
    }
#pragma unroll
    for (int o = 16; o; o >>= 1) s += __shfl_xor_sync(0xffffffffu, s, o);
    if ((t & 31) == 0) wsum[t >> 5] = s;
    __syncthreads();
    if (t == 0) {
        int tot = 0;
#pragma unroll
        for (int w = 0; w < 8; w++) tot += wsum[w];
        g_bsum[blockIdx.x] = tot;
    }
}

// Phase 2: single block, exclusive scan of block partials; also g_off[n]
__global__ void k_scan2(int nb, int n) {
    __shared__ int sh[SCAN_MAXBLK];
    int t = threadIdx.x;  // 64 threads
    int v = (t < nb) ? g_bsum[t] : 0;
    sh[t] = v;
    __syncthreads();
    for (int o = 1; o < SCAN_MAXBLK; o <<= 1) {
        int p = (t >= o) ? sh[t - o] : 0;
        __syncthreads();
        sh[t] += p;
        __syncthreads();
    }
    if (t < nb) g_boff[t] = sh[t] - v;        // exclusive
    if (t == SCAN_MAXBLK - 1) g_off[n] = sh[t];  // total = E
}

// Phase 3: intra-block exclusive scan + global offset; write g_off/g_cur
__global__ void k_scan3(int n) {
    __shared__ int tsum[256];
    __shared__ int woff[8];
    int t = threadIdx.x;
    int base = blockIdx.x * SCAN_ELEMS + t * 4;

    int v[4];
    int s = 0;
#pragma unroll
    for (int u = 0; u < 4; u++) {
        int i = base + u;
        v[u] = (i < n) ? g_cnt[i] : 0;
        s += v[u];
    }
    // warp inclusive scan of thread sums
    int lane = t & 31, wid = t >> 5;
    int inc = s;
#pragma unroll
    for (int o = 1; o < 32; o <<= 1) {
        int p = __shfl_up_sync(0xffffffffu, inc, o);
        if (lane >= o) inc += p;
    }
    if (lane == 31) tsum[wid] = inc;
    __syncthreads();
    if (t < 8) {
        int wv = tsum[t];
        int wi = wv;
#pragma unroll
        for (int o = 1; o < 8; o <<= 1) {
            int p = __shfl_up_sync(0xffu, wi, o);
            if (t >= o) wi += p;
        }
        woff[t] = wi - wv;   // exclusive warp offset
    }
    __syncthreads();

    int excl = g_boff[blockIdx.x] + woff[wid] + (inc - s);
#pragma unroll
    for (int u = 0; u < 4; u++) {
        int i = base + u;
        if (i < n) {
            g_off[i] = excl;
            g_cur[i] = excl;
            excl += v[u];
        }
    }
}

// bin edges into CSR by target
__global__ void k_fill(const int* __restrict__ ei, int E) {
    int e = blockIdx.x * blockDim.x + threadIdx.x;
    if (e >= E) return;
    int r = ei[e];
    int c = ei[E + e];
    int pos = atomicAdd(&g_cur[c], 1);
    g_src[pos] = r;
}

// ---------------------------------------------------------------------------
// GEMM: g_h[r][c] = dis[r] * (sum_k x[r][k]*W[c][k] + b[c])
// 128x128 tile per 256-thread block; 8x8 outputs per thread.
#define XCHUNK 16
#define XBUF (XCHUNK * 128)   // 2048 floats per buffer

__global__ __launch_bounds__(256, 2)
void k_gemm(const float* __restrict__ x, const float* __restrict__ W,
            const float* __restrict__ b, int n) {
    extern __shared__ float sm[];
    float* Ws = sm;                 // [128][128] : Ws[k][c] = W[c][k]
    float* xs = sm + D * D;         // [2][XCHUNK][128] : xs[buf][kl][row]

    int t  = threadIdx.x;
    int tx = t & 15;                // 16 col-groups
    int ty = t >> 4;                // 16 row-groups
    int row0 = blockIdx.x * 128;

    // Load W transposed into Ws[k][c] (conflict-free STS)
    for (int i = t; i < (D * D) / 4; i += 256) {
        int c  = i & 127;
        int k4 = (i >> 7) << 2;
        float4 w = *(const float4*)&W[c * D + k4];
        Ws[(k4 + 0) * D + c] = w.x;
        Ws[(k4 + 1) * D + c] = w.y;
        Ws[(k4 + 2) * D + c] = w.z;
        Ws[(k4 + 3) * D + c] = w.w;
    }

    // Prologue: stage chunk 0 (k-major)
    {
        int j0 = t * 2;
#pragma unroll
        for (int u = 0; u < 2; u++) {
            int j = j0 + u;
            int r = j >> 2;
            int kk = (j & 3) * 4;
            int row = row0 + r;
            float4 v = make_float4(0.f, 0.f, 0.f, 0.f);
            if (row < n) v = *(const float4*)&x[row * D + kk];
            xs[(kk + 0) * 128 + r] = v.x;
            xs[(kk + 1) * 128 + r] = v.y;
            xs[(kk + 2) * 128 + r] = v.z;
            xs[(kk + 3) * 128 + r] = v.w;
        }
    }
    __syncthreads();

    float acc[8][8];
#pragma unroll
    for (int i = 0; i < 8; i++)
#pragma unroll
        for (int j = 0; j < 8; j++) acc[i][j] = 0.f;

    for (int c = 0; c < D / XCHUNK; c++) {
        float4 p[2];
        if (c < D / XCHUNK - 1) {
            int k0 = (c + 1) * XCHUNK;
            int j0 = t * 2;
#pragma unroll
            for (int u = 0; u < 2; u++) {
                int j = j0 + u;
                int r = j >> 2;
                int kk = (j & 3) * 4;
                int row = row0 + r;
                p[u] = make_float4(0.f, 0.f, 0.f, 0.f);
                if (row < n) p[u] = *(const float4*)&x[row * D + k0 + kk];
            }
        }

        const float* xb = &xs[(c & 1) * XBUF];
#pragma unroll
        for (int kl = 0; kl < XCHUNK; kl++) {
            const float* wrow = &Ws[(c * XCHUNK + kl) * D];
            float4 b0 = *(const float4*)&wrow[tx * 4];
            float4 b1 = *(const float4*)&wrow[64 + tx * 4];
            // vectorized rA: 2x LDS.128 (broadcast within half-warp)
            float4 a0 = *(const float4*)&xb[kl * 128 + ty * 8];
            float4 a1 = *(const float4*)&xb[kl * 128 + ty * 8 + 4];
            float rA[8] = {a0.x, a0.y, a0.z, a0.w, a1.x, a1.y, a1.z, a1.w};
#pragma unroll
            for (int i = 0; i < 8; i++) {
                acc[i][0] += rA[i] * b0.x;
                acc[i][1] += rA[i] * b0.y;
                acc[i][2] += rA[i] * b0.z;
                acc[i][3] += rA[i] * b0.w;
                acc[i][4] += rA[i] * b1.x;
                acc[i][5] += rA[i] * b1.y;
                acc[i][6] += rA[i] * b1.z;
                acc[i][7] += rA[i] * b1.w;
            }
        }

        if (c < D / XCHUNK - 1) {
            float* dst = &xs[((c + 1) & 1) * XBUF];
            int j0 = t * 2;
#pragma unroll
            for (int u = 0; u < 2; u++) {
                int j = j0 + u;
                int r = j >> 2;
                int kk = (j & 3) * 4;
                dst[(kk + 0) * 128 + r] = p[u].x;
                dst[(kk + 1) * 128 + r] = p[u].y;
                dst[(kk + 2) * 128 + r] = p[u].z;
                dst[(kk + 3) * 128 + r] = p[u].w;
            }
        }
        __syncthreads();
    }

    // Epilogue: += bias, * dis[row], store
    float4 bv0 = *(const float4*)&b[tx * 4];
    float4 bv1 = *(const float4*)&b[64 + tx * 4];
#pragma unroll
    for (int i = 0; i < 8; i++) {
        int row = row0 + ty * 8 + i;
        if (row >= n) break;
        float dv = g_dis[row];
        float4 o0, o1;
        o0.x = (acc[i][0] + bv0.x) * dv;
        o0.y = (acc[i][1] + bv0.y) * dv;
        o0.z = (acc[i][2] + bv0.z) * dv;
        o0.w = (acc[i][3] + bv0.w) * dv;
        o1.x = (acc[i][4] + bv1.x) * dv;
        o1.y = (acc[i][5] + bv1.y) * dv;
        o1.z = (acc[i][6] + bv1.z) * dv;
        o1.w = (acc[i][7] + bv1.w) * dv;
        *(float4*)&g_h[row * D + tx * 4] = o0;
        *(float4*)&g_h[row * D + 64 + tx * 4] = o1;
    }
}

// ---------------------------------------------------------------------------
// Fused gather + self-loop + ReLU + LayerNorm + residual. Warp per node.
// (serial gather — known good)
__global__ void k_agg(const float* __restrict__ x,
                      const float* __restrict__ gamma,
                      const float* __restrict__ beta,
                      float* __restrict__ out, int n) {
    int node = (blockIdx.x * blockDim.x + threadIdx.x) >> 5;
    int lane = threadIdx.x & 31;
    if (node >= n) return;

    float dc = g_dis[node];
    int lo = g_off[node], hi = g_off[node + 1];

    float4 acc = make_float4(0.f, 0.f, 0.f, 0.f);
    for (int i = lo; i < hi; i++) {
        int r = g_src[i];  // lane-uniform (warp-broadcast load)
        float4 m = *(const float4*)&g_h[r * D + lane * 4];
        acc.x += m.x; acc.y += m.y; acc.z += m.z; acc.w += m.w;
    }
    // self loop
    float4 hs = *(const float4*)&g_h[node * D + lane * 4];
    acc.x += hs.x; acc.y += hs.y; acc.z += hs.z; acc.w += hs.w;

    float4 v;
    v.x = fmaxf(acc.x * dc, 0.f);
    v.y = fmaxf(acc.y * dc, 0.f);
    v.z = fmaxf(acc.z * dc, 0.f);
    v.w = fmaxf(acc.w * dc, 0.f);

    float s  = v.x + v.y + v.z + v.w;
    float ss = v.x * v.x + v.y * v.y + v.z * v.z + v.w * v.w;
#pragma unroll
    for (int o = 16; o; o >>= 1) {
        s  += __shfl_xor_sync(0xffffffffu, s,  o);
        ss += __shfl_xor_sync(0xffffffffu, ss, o);
    }
    float mu  = s * (1.f / 128.f);
    float var = ss * (1.f / 128.f) - mu * mu;
    float inv = rsqrtf(var + 1e-5f);

    float4 g  = *(const float4*)&gamma[lane * 4];
    float4 be = *(const float4*)&beta[lane * 4];
    float4 xv = *(const float4*)&x[node * D + lane * 4];

    float4 o;
    o.x = (v.x - mu) * inv * g.x + be.x + xv.x;
    o.y = (v.y - mu) * inv * g.y + be.y + xv.y;
    o.z = (v.z - mu) * inv * g.z + be.z + xv.z;
    o.w = (v.w - mu) * inv * g.w + be.w + xv.w;
    *(float4*)&out[node * D + lane * 4] = o;
}

// ---------------------------------------------------------------------------
extern "C" void kernel_launch(void* const* d_in, const int* in_sizes, int n_in,
                              void* d_out, int out_size) {
    const float* x     = (const float*)d_in[0];
    const int*   ei    = (const int*)d_in[1];    // int32 (JAX x64 disabled)
    const float* W     = (const float*)d_in[2];
    const float* b     = (const float*)d_in[3];
    const float* gamma = (const float*)d_in[4];
    const float* beta  = (const float*)d_in[5];
    float*       out   = (float*)d_out;

    int n = in_sizes[0] / D;
    int E = in_sizes[1] / 2;
    int nb = (n + SCAN_ELEMS - 1) / SCAN_ELEMS;

    // R6 launch order preserved (scan/fill AFTER gemm).
    k_zero<<<(n + 255) / 256, 256>>>(n);
    k_count<<<(E + 255) / 256, 256>>>(ei, E);
    k_dis<<<(n + 255) / 256, 256>>>(n);

    int smem = (D * D + 2 * XBUF) * sizeof(float);  // 80 KB
    cudaFuncSetAttribute(k_gemm, cudaFuncAttributeMaxDynamicSharedMemorySize, smem);
    k_gemm<<<(n + 127) / 128, 256, smem>>>(x, W, b, n);

    k_scan1<<<nb, 256>>>(n);
    k_scan2<<<1, SCAN_MAXBLK>>>(nb, n);
    k_scan3<<<nb, 256>>>(n);
    k_fill<<<(E + 255) / 256, 256>>>(ei, E);

    k_agg<<<(n + 7) / 8, 256>>>(x, gamma, beta, out, n);
}

// round 9
// speedup vs baseline: 2.1747x; 1.0595x over previous
#include <cuda_runtime.h>
#include <stdint.h>

#define D 128
#define NMAX 50048
#define EMAX 1000000
#define SCAN_ELEMS 1024              // elements per scan block (256 thr x 4)
#define SCAN_MAXBLK 64

// Scratch (__device__ globals — allocation-free rule)
__device__ float g_h[NMAX * D];      // h' = dis[r] * (x @ W^T + b)[r]
__device__ float g_dis[NMAX];        // (deg+1)^-0.5
__device__ int   g_degi[NMAX];       // edge count per source
__device__ int   g_cnt[NMAX];        // edge count per target
__device__ int   g_off[NMAX + 1];    // CSR offsets (by target)
__device__ int   g_cur[NMAX];        // fill cursors
__device__ int   g_src[EMAX];        // CSR payload: source index per edge
__device__ int   g_bsum[SCAN_MAXBLK];
__device__ int   g_boff[SCAN_MAXBLK];

// ---------------------------------------------------------------------------
__global__ void k_zero(int n) {
    int i = blockIdx.x * blockDim.x + threadIdx.x;
    if (i < n) { g_degi[i] = 0; g_cnt[i] = 0; }
}

__global__ void k_count(const int* __restrict__ ei, int E) {
    int e = blockIdx.x * blockDim.x + threadIdx.x;
    if (e >= E) return;
    atomicAdd(&g_degi[ei[e]], 1);
    atomicAdd(&g_cnt[ei[E + e]], 1);
}

__global__ void k_dis(int n) {
    int i = blockIdx.x * blockDim.x + threadIdx.x;
    if (i < n) g_dis[i] = rsqrtf((float)(g_degi[i] + 1));
}

// --- parallel exclusive scan (R7, verified) -------------------------------
__global__ void k_scan1(int n) {
    __shared__ int wsum[8];
    int t = threadIdx.x;
    int base = blockIdx.x * SCAN_ELEMS + t * 4;
    int s = 0;
#pragma unroll
    for (int u = 0; u < 4; u++) {
        int i = base + u;
        if (i < n) s += g_cnt[i];
    }
#pragma unroll
    for (int o = 16; o; o >>= 1) s += __shfl_xor_sync(0xffffffffu, s, o);
    if ((t & 31) == 0) wsum[t >> 5] = s;
    __syncthreads();
    if (t == 0) {
        int tot = 0;
#pragma unroll
        for (int w = 0; w < 8; w++) tot += wsum[w];
        g_bsum[blockIdx.x] = tot;
    }
}

__global__ void k_scan2(int nb, int n) {
    __shared__ int sh[SCAN_MAXBLK];
    int t = threadIdx.x;
    int v = (t < nb) ? g_bsum[t] : 0;
    sh[t] = v;
    __syncthreads();
    for (int o = 1; o < SCAN_MAXBLK; o <<= 1) {
        int p = (t >= o) ? sh[t - o] : 0;
        __syncthreads();
        sh[t] += p;
        __syncthreads();
    }
    if (t < nb) g_boff[t] = sh[t] - v;
    if (t == SCAN_MAXBLK - 1) g_off[n] = sh[t];
}

__global__ void k_scan3(int n) {
    __shared__ int tsum[256];
    __shared__ int woff[8];
    int t = threadIdx.x;
    int base = blockIdx.x * SCAN_ELEMS + t * 4;

    int v[4];
    int s = 0;
#pragma unroll
    for (int u = 0; u < 4; u++) {
        int i = base + u;
        v[u] = (i < n) ? g_cnt[i] : 0;
        s += v[u];
    }
    int lane = t & 31, wid = t >> 5;
    int inc = s;
#pragma unroll
    for (int o = 1; o < 32; o <<= 1) {
        int p = __shfl_up_sync(0xffffffffu, inc, o);
        if (lane >= o) inc += p;
    }
    if (lane == 31) tsum[wid] = inc;
    __syncthreads();
    if (t < 8) {
        int wv = tsum[t];
        int wi = wv;
#pragma unroll
        for (int o = 1; o < 8; o <<= 1) {
            int p = __shfl_up_sync(0xffu, wi, o);
            if (t >= o) wi += p;
        }
        woff[t] = wi - wv;
    }
    __syncthreads();

    int excl = g_boff[blockIdx.x] + woff[wid] + (inc - s);
#pragma unroll
    for (int u = 0; u < 4; u++) {
        int i = base + u;
        if (i < n) {
            g_off[i] = excl;
            g_cur[i] = excl;
            excl += v[u];
        }
    }
}

__global__ void k_fill(const int* __restrict__ ei, int E) {
    int e = blockIdx.x * blockDim.x + threadIdx.x;
    if (e >= E) return;
    int r = ei[e];
    int c = ei[E + e];
    int pos = atomicAdd(&g_cur[c], 1);
    g_src[pos] = r;
}

// ---------------------------------------------------------------------------
// tf32 mma.sync GEMM: g_h[r][c] = dis[r] * (sum_k x[r][k]*W[c][k] + b[c])
// A = x tile (row-major), B = W (row-major [c][k] == col-major KxN). tf32 in
// padded smem (132-float rows -> all fragment LDS conflict-free).
// Block 256 thr = 8 warps, warp grid 4(m) x 2(n): 32 rows x 64 cols per warp.
// ---------------------------------------------------------------------------
#define XPAD 132
#define SM_FLOATS (2 * 128 * XPAD + 256)

__device__ __forceinline__ uint32_t tf32b(float f) {
    uint32_t r;
    asm("cvt.rna.tf32.f32 %0, %1;" : "=r"(r) : "f"(f));
    return r;
}

#define MMA_TF32(cc, aa, bb0, bb1)                                         \
    asm volatile(                                                          \
        "mma.sync.aligned.m16n8k8.row.col.f32.tf32.tf32.f32 "              \
        "{%0,%1,%2,%3}, {%4,%5,%6,%7}, {%8,%9}, {%0,%1,%2,%3};"            \
        : "+f"(cc[0]), "+f"(cc[1]), "+f"(cc[2]), "+f"(cc[3])               \
        : "r"(aa[0]), "r"(aa[1]), "r"(aa[2]), "r"(aa[3]),                  \
          "r"(bb0), "r"(bb1))

__global__ __launch_bounds__(256, 1)
void k_gemm(const float* __restrict__ x, const float* __restrict__ W,
            const float* __restrict__ bias, int n) {
    extern __shared__ float sm[];
    float* ws    = sm;                     // [128][XPAD] W (tf32 bits)
    float* xs    = sm + 128 * XPAD;        // [128][XPAD] x tile (tf32 bits)
    float* dis_s = sm + 2 * 128 * XPAD;    // [128]
    float* b_s   = dis_s + 128;            // [128]

    int t = threadIdx.x;
    int w = t >> 5;
    int lane = t & 31;
    int g  = lane >> 2;     // group id 0..7
    int tg = lane & 3;      // thread-in-group 0..3
    int mw = w & 3;         // warp row-group (32 rows)
    int nw = w >> 2;        // warp col-group (64 cols)
    int row0 = blockIdx.x * 128;

    // Stage W (tf32)
    for (int i = t; i < 4096; i += 256) {
        int r  = i >> 5;
        int k4 = (i & 31) * 4;
        float4 v = *(const float4*)&W[r * D + k4];
        uint4 tv;
        tv.x = tf32b(v.x); tv.y = tf32b(v.y);
        tv.z = tf32b(v.z); tv.w = tf32b(v.w);
        *(uint4*)&ws[r * XPAD + k4] = tv;
    }
    // Stage x tile (tf32), zero-padded OOB rows
    for (int i = t; i < 4096; i += 256) {
        int r  = i >> 5;
        int k4 = (i & 31) * 4;
        int row = row0 + r;
        float4 v = make_float4(0.f, 0.f, 0.f, 0.f);
        if (row < n) v = *(const float4*)&x[row * D + k4];
        uint4 tv;
        tv.x = tf32b(v.x); tv.y = tf32b(v.y);
        tv.z = tf32b(v.z); tv.w = tf32b(v.w);
        *(uint4*)&xs[r * XPAD + k4] = tv;
    }
    if (t < 128) {
        int row = row0 + t;
        dis_s[t] = (row < n) ? g_dis[row] : 0.f;
        b_s[t] = bias[t];
    }
    __syncthreads();

    float c[2][8][4];
#pragma unroll
    for (int mi = 0; mi < 2; mi++)
#pragma unroll
        for (int ni = 0; ni < 8; ni++)
#pragma unroll
            for (int j = 0; j < 4; j++) c[mi][ni][j] = 0.f;

    const float* xbase = &xs[(mw * 32) * XPAD];
    const float* wbase = &ws[(nw * 64) * XPAD];

#pragma unroll
    for (int k0 = 0; k0 < 128; k0 += 8) {
        uint32_t a[2][4];
#pragma unroll
        for (int mi = 0; mi < 2; mi++) {
            const float* ab = &xbase[(mi * 16) * XPAD + k0];
            a[mi][0] = __float_as_uint(ab[g * XPAD + tg]);
            a[mi][1] = __float_as_uint(ab[(g + 8) * XPAD + tg]);
            a[mi][2] = __float_as_uint(ab[g * XPAD + tg + 4]);
            a[mi][3] = __float_as_uint(ab[(g + 8) * XPAD + tg + 4]);
        }
#pragma unroll
        for (int ni = 0; ni < 8; ni++) {
            const float* bb = &wbase[(ni * 8 + g) * XPAD + k0];
            uint32_t b0 = __float_as_uint(bb[tg]);
            uint32_t b1 = __float_as_uint(bb[tg + 4]);
            MMA_TF32(c[0][ni], a[0], b0, b1);
            MMA_TF32(c[1][ni], a[1], b0, b1);
        }
    }

    // Epilogue: (acc + bias) * dis[row]; float2 stores
#pragma unroll
    for (int mi = 0; mi < 2; mi++) {
#pragma unroll
        for (int ni = 0; ni < 8; ni++) {
            int lr  = mw * 32 + mi * 16 + g;
            int col = nw * 64 + ni * 8 + tg * 2;
            float bv0 = b_s[col], bv1 = b_s[col + 1];
            int row = row0 + lr;
            if (row < n) {
                float dv = dis_s[lr];
                float2 o;
                o.x = (c[mi][ni][0] + bv0) * dv;
                o.y = (c[mi][ni][1] + bv1) * dv;
                *(float2*)&g_h[row * D + col] = o;
            }
            int row2 = row0 + lr + 8;
            if (row2 < n) {
                float dv = dis_s[lr + 8];
                float2 o;
                o.x = (c[mi][ni][2] + bv0) * dv;
                o.y = (c[mi][ni][3] + bv1) * dv;
                *(float2*)&g_h[row2 * D + col] = o;
            }
        }
    }
}

// ---------------------------------------------------------------------------
// Fused gather + self-loop + ReLU + LayerNorm + residual. Warp per node.
__global__ void k_agg(const float* __restrict__ x,
                      const float* __restrict__ gamma,
                      const float* __restrict__ beta,
                      float* __restrict__ out, int n) {
    int node = (blockIdx.x * blockDim.x + threadIdx.x) >> 5;
    int lane = threadIdx.x & 31;
    if (node >= n) return;

    float dc = g_dis[node];
    int lo = g_off[node], hi = g_off[node + 1];

    float4 acc = make_float4(0.f, 0.f, 0.f, 0.f);
    for (int i = lo; i < hi; i++) {
        int r = g_src[i];
        float4 m = *(const float4*)&g_h[r * D + lane * 4];
        acc.x += m.x; acc.y += m.y; acc.z += m.z; acc.w += m.w;
    }
    float4 hs = *(const float4*)&g_h[node * D + lane * 4];
    acc.x += hs.x; acc.y += hs.y; acc.z += hs.z; acc.w += hs.w;

    float4 v;
    v.x = fmaxf(acc.x * dc, 0.f);
    v.y = fmaxf(acc.y * dc, 0.f);
    v.z = fmaxf(acc.z * dc, 0.f);
    v.w = fmaxf(acc.w * dc, 0.f);

    float s  = v.x + v.y + v.z + v.w;
    float ss = v.x * v.x + v.y * v.y + v.z * v.z + v.w * v.w;
#pragma unroll
    for (int o = 16; o; o >>= 1) {
        s  += __shfl_xor_sync(0xffffffffu, s,  o);
        ss += __shfl_xor_sync(0xffffffffu, ss, o);
    }
    float mu  = s * (1.f / 128.f);
    float var = ss * (1.f / 128.f) - mu * mu;
    float inv = rsqrtf(var + 1e-5f);

    float4 g  = *(const float4*)&gamma[lane * 4];
    float4 be = *(const float4*)&beta[lane * 4];
    float4 xv = *(const float4*)&x[node * D + lane * 4];

    float4 o;
    o.x = (v.x - mu) * inv * g.x + be.x + xv.x;
    o.y = (v.y - mu) * inv * g.y + be.y + xv.y;
    o.z = (v.z - mu) * inv * g.z + be.z + xv.z;
    o.w = (v.w - mu) * inv * g.w + be.w + xv.w;
    *(float4*)&out[node * D + lane * 4] = o;
}

// ---------------------------------------------------------------------------
extern "C" void kernel_launch(void* const* d_in, const int* in_sizes, int n_in,
                              void* d_out, int out_size) {
    const float* x     = (const float*)d_in[0];
    const int*   ei    = (const int*)d_in[1];
    const float* W     = (const float*)d_in[2];
    const float* b     = (const float*)d_in[3];
    const float* gamma = (const float*)d_in[4];
    const float* beta  = (const float*)d_in[5];
    float*       out   = (float*)d_out;

    int n = in_sizes[0] / D;
    int E = in_sizes[1] / 2;
    int nb = (n + SCAN_ELEMS - 1) / SCAN_ELEMS;

    k_zero<<<(n + 255) / 256, 256>>>(n);
    k_count<<<(E + 255) / 256, 256>>>(ei, E);
    k_dis<<<(n + 255) / 256, 256>>>(n);

    int smem = SM_FLOATS * sizeof(float);  // ~133 KB
    cudaFuncSetAttribute(k_gemm, cudaFuncAttributeMaxDynamicSharedMemorySize, smem);
    k_gemm<<<(n + 127) / 128, 256, smem>>>(x, W, b, n);

    k_scan1<<<nb, 256>>>(n);
    k_scan2<<<1, SCAN_MAXBLK>>>(nb, n);
    k_scan3<<<nb, 256>>>(n);
    k_fill<<<(E + 255) / 256, 256>>>(ei, E);

    k_agg<<<(n + 7) / 8, 256>>>(x, gamma, beta, out, n);
}

// round 10
// speedup vs baseline: 2.4678x; 1.1348x over previous
#include <cuda_runtime.h>
#include <stdint.h>

#define D 128
#define NMAX 50048
#define EMAX 1000000
#define SCAN_ELEMS 1024              // elements per scan block (256 thr x 4)
#define SCAN_MAXBLK 64

// Scratch (__device__ globals — allocation-free rule)
__device__ float g_h[NMAX * D];      // h' = dis[r] * (x @ W^T + b)[r]
__device__ float g_dis[NMAX];        // (deg+1)^-0.5
__device__ int   g_degi[NMAX];       // edge count per source
__device__ int   g_cnt[NMAX];        // edge count per target
__device__ int   g_off[NMAX + 1];    // CSR offsets (by target)
__device__ int   g_cur[NMAX];        // fill cursors
__device__ int   g_src[EMAX];        // CSR payload: source index per edge
__device__ int   g_bsum[SCAN_MAXBLK];
__device__ int   g_boff[SCAN_MAXBLK];

// ---------------------------------------------------------------------------
__global__ void k_zero(int n) {
    int i = blockIdx.x * blockDim.x + threadIdx.x;
    if (i < n) { g_degi[i] = 0; g_cnt[i] = 0; }
}

__global__ void k_count(const int* __restrict__ ei, int E) {
    int e = blockIdx.x * blockDim.x + threadIdx.x;
    if (e >= E) return;
    atomicAdd(&g_degi[ei[e]], 1);
    atomicAdd(&g_cnt[ei[E + e]], 1);
}

__global__ void k_dis(int n) {
    int i = blockIdx.x * blockDim.x + threadIdx.x;
    if (i < n) g_dis[i] = rsqrtf((float)(g_degi[i] + 1));
}

// --- parallel exclusive scan (verified) ------------------------------------
__global__ void k_scan1(int n) {
    __shared__ int wsum[8];
    int t = threadIdx.x;
    int base = blockIdx.x * SCAN_ELEMS + t * 4;
    int s = 0;
#pragma unroll
    for (int u = 0; u < 4; u++) {
        int i = base + u;
        if (i < n) s += g_cnt[i];
    }
#pragma unroll
    for (int o = 16; o; o >>= 1) s += __shfl_xor_sync(0xffffffffu, s, o);
    if ((t & 31) == 0) wsum[t >> 5] = s;
    __syncthreads();
    if (t == 0) {
        int tot = 0;
#pragma unroll
        for (int w = 0; w < 8; w++) tot += wsum[w];
        g_bsum[blockIdx.x] = tot;
    }
}

__global__ void k_scan2(int nb, int n) {
    __shared__ int sh[SCAN_MAXBLK];
    int t = threadIdx.x;
    int v = (t < nb) ? g_bsum[t] : 0;
    sh[t] = v;
    __syncthreads();
    for (int o = 1; o < SCAN_MAXBLK; o <<= 1) {
        int p = (t >= o) ? sh[t - o] : 0;
        __syncthreads();
        sh[t] += p;
        __syncthreads();
    }
    if (t < nb) g_boff[t] = sh[t] - v;
    if (t == SCAN_MAXBLK - 1) g_off[n] = sh[t];
}

__global__ void k_scan3(int n) {
    __shared__ int tsum[256];
    __shared__ int woff[8];
    int t = threadIdx.x;
    int base = blockIdx.x * SCAN_ELEMS + t * 4;

    int v[4];
    int s = 0;
#pragma unroll
    for (int u = 0; u < 4; u++) {
        int i = base + u;
        v[u] = (i < n) ? g_cnt[i] : 0;
        s += v[u];
    }
    int lane = t & 31, wid = t >> 5;
    int inc = s;
#pragma unroll
    for (int o = 1; o < 32; o <<= 1) {
        int p = __shfl_up_sync(0xffffffffu, inc, o);
        if (lane >= o) inc += p;
    }
    if (lane == 31) tsum[wid] = inc;
    __syncthreads();
    if (t < 8) {
        int wv = tsum[t];
        int wi = wv;
#pragma unroll
        for (int o = 1; o < 8; o <<= 1) {
            int p = __shfl_up_sync(0xffu, wi, o);
            if (t >= o) wi += p;
        }
        woff[t] = wi - wv;
    }
    __syncthreads();

    int excl = g_boff[blockIdx.x] + woff[wid] + (inc - s);
#pragma unroll
    for (int u = 0; u < 4; u++) {
        int i = base + u;
        if (i < n) {
            g_off[i] = excl;
            g_cur[i] = excl;
            excl += v[u];
        }
    }
}

__global__ void k_fill(const int* __restrict__ ei, int E) {
    int e = blockIdx.x * blockDim.x + threadIdx.x;
    if (e >= E) return;
    int r = ei[e];
    int c = ei[E + e];
    int pos = atomicAdd(&g_cur[c], 1);
    g_src[pos] = r;
}

// ---------------------------------------------------------------------------
// tf32 mma.sync GEMM: g_h[r][c] = dis[r] * (sum_k x[r][k]*W[c][k] + b[c])
// 512 threads = 16 warps, warp grid 4(m) x 4(n): 32 rows x 32 cols per warp.
// ---------------------------------------------------------------------------
#define XPAD 132
#define SM_FLOATS (2 * 128 * XPAD + 256)

__device__ __forceinline__ uint32_t tf32b(float f) {
    uint32_t r;
    asm("cvt.rna.tf32.f32 %0, %1;" : "=r"(r) : "f"(f));
    return r;
}

#define MMA_TF32(cc, aa, bb0, bb1)                                         \
    asm volatile(                                                          \
        "mma.sync.aligned.m16n8k8.row.col.f32.tf32.tf32.f32 "              \
        "{%0,%1,%2,%3}, {%4,%5,%6,%7}, {%8,%9}, {%0,%1,%2,%3};"            \
        : "+f"(cc[0]), "+f"(cc[1]), "+f"(cc[2]), "+f"(cc[3])               \
        : "r"(aa[0]), "r"(aa[1]), "r"(aa[2]), "r"(aa[3]),                  \
          "r"(bb0), "r"(bb1))

__global__ __launch_bounds__(512, 1)
void k_gemm(const float* __restrict__ x, const float* __restrict__ W,
            const float* __restrict__ bias, int n) {
    extern __shared__ float sm[];
    float* ws    = sm;                     // [128][XPAD] W (tf32 bits)
    float* xs    = sm + 128 * XPAD;        // [128][XPAD] x tile (tf32 bits)
    float* dis_s = sm + 2 * 128 * XPAD;    // [128]
    float* b_s   = dis_s + 128;            // [128]

    int t = threadIdx.x;
    int w = t >> 5;
    int lane = t & 31;
    int g  = lane >> 2;     // group id 0..7
    int tg = lane & 3;      // thread-in-group 0..3
    int mw = w & 3;         // warp row-group (32 rows)
    int nw = w >> 2;        // warp col-group (32 cols)
    int row0 = blockIdx.x * 128;

    // Stage W (tf32)
    for (int i = t; i < 4096; i += 512) {
        int r  = i >> 5;
        int k4 = (i & 31) * 4;
        float4 v = *(const float4*)&W[r * D + k4];
        uint4 tv;
        tv.x = tf32b(v.x); tv.y = tf32b(v.y);
        tv.z = tf32b(v.z); tv.w = tf32b(v.w);
        *(uint4*)&ws[r * XPAD + k4] = tv;
    }
    // Stage x tile (tf32), zero-padded OOB rows
    for (int i = t; i < 4096; i += 512) {
        int r  = i >> 5;
        int k4 = (i & 31) * 4;
        int row = row0 + r;
        float4 v = make_float4(0.f, 0.f, 0.f, 0.f);
        if (row < n) v = *(const float4*)&x[row * D + k4];
        uint4 tv;
        tv.x = tf32b(v.x); tv.y = tf32b(v.y);
        tv.z = tf32b(v.z); tv.w = tf32b(v.w);
        *(uint4*)&xs[r * XPAD + k4] = tv;
    }
    if (t < 128) {
        int row = row0 + t;
        dis_s[t] = (row < n) ? g_dis[row] : 0.f;
        b_s[t] = bias[t];
    }
    __syncthreads();

    float c[2][4][4];
#pragma unroll
    for (int mi = 0; mi < 2; mi++)
#pragma unroll
        for (int ni = 0; ni < 4; ni++)
#pragma unroll
            for (int j = 0; j < 4; j++) c[mi][ni][j] = 0.f;

    const float* xbase = &xs[(mw * 32) * XPAD];
    const float* wbase = &ws[(nw * 32) * XPAD];

#pragma unroll
    for (int k0 = 0; k0 < 128; k0 += 8) {
        uint32_t a[2][4];
#pragma unroll
        for (int mi = 0; mi < 2; mi++) {
            const float* ab = &xbase[(mi * 16) * XPAD + k0];
            a[mi][0] = __float_as_uint(ab[g * XPAD + tg]);
            a[mi][1] = __float_as_uint(ab[(g + 8) * XPAD + tg]);
            a[mi][2] = __float_as_uint(ab[g * XPAD + tg + 4]);
            a[mi][3] = __float_as_uint(ab[(g + 8) * XPAD + tg + 4]);
        }
#pragma unroll
        for (int ni = 0; ni < 4; ni++) {
            const float* bb = &wbase[(ni * 8 + g) * XPAD + k0];
            uint32_t b0 = __float_as_uint(bb[tg]);
            uint32_t b1 = __float_as_uint(bb[tg + 4]);
            MMA_TF32(c[0][ni], a[0], b0, b1);
            MMA_TF32(c[1][ni], a[1], b0, b1);
        }
    }

    // Epilogue: (acc + bias) * dis[row]; float2 stores
#pragma unroll
    for (int mi = 0; mi < 2; mi++) {
#pragma unroll
        for (int ni = 0; ni < 4; ni++) {
            int lr  = mw * 32 + mi * 16 + g;
            int col = nw * 32 + ni * 8 + tg * 2;
            float bv0 = b_s[col], bv1 = b_s[col + 1];
            int row = row0 + lr;
            if (row < n) {
                float dv = dis_s[lr];
                float2 o;
                o.x = (c[mi][ni][0] + bv0) * dv;
                o.y = (c[mi][ni][1] + bv1) * dv;
                *(float2*)&g_h[row * D + col] = o;
            }
            int row2 = row0 + lr + 8;
            if (row2 < n) {
                float dv = dis_s[lr + 8];
                float2 o;
                o.x = (c[mi][ni][2] + bv0) * dv;
                o.y = (c[mi][ni][3] + bv1) * dv;
                *(float2*)&g_h[row2 * D + col] = o;
            }
        }
    }
}

// ---------------------------------------------------------------------------
// Fused gather + self-loop + ReLU + LayerNorm + residual. Warp per node.
__global__ void k_agg(const float* __restrict__ x,
                      const float* __restrict__ gamma,
                      const float* __restrict__ beta,
                      float* __restrict__ out, int n) {
    int node = (blockIdx.x * blockDim.x + threadIdx.x) >> 5;
    int lane = threadIdx.x & 31;
    if (node >= n) return;

    float dc = g_dis[node];
    int lo = g_off[node], hi = g_off[node + 1];

    float4 acc = make_float4(0.f, 0.f, 0.f, 0.f);
    for (int i = lo; i < hi; i++) {
        int r = g_src[i];
        float4 m = *(const float4*)&g_h[r * D + lane * 4];
        acc.x += m.x; acc.y += m.y; acc.z += m.z; acc.w += m.w;
    }
    float4 hs = *(const float4*)&g_h[node * D + lane * 4];
    acc.x += hs.x; acc.y += hs.y; acc.z += hs.z; acc.w += hs.w;

    float4 v;
    v.x = fmaxf(acc.x * dc, 0.f);
    v.y = fmaxf(acc.y * dc, 0.f);
    v.z = fmaxf(acc.z * dc, 0.f);
    v.w = fmaxf(acc.w * dc, 0.f);

    float s  = v.x + v.y + v.z + v.w;
    float ss = v.x * v.x + v.y * v.y + v.z * v.z + v.w * v.w;
#pragma unroll
    for (int o = 16; o; o >>= 1) {
        s  += __shfl_xor_sync(0xffffffffu, s,  o);
        ss += __shfl_xor_sync(0xffffffffu, ss, o);
    }
    float mu  = s * (1.f / 128.f);
    float var = ss * (1.f / 128.f) - mu * mu;
    float inv = rsqrtf(var + 1e-5f);

    float4 g  = *(const float4*)&gamma[lane * 4];
    float4 be = *(const float4*)&beta[lane * 4];
    float4 xv = *(const float4*)&x[node * D + lane * 4];

    float4 o;
    o.x = (v.x - mu) * inv * g.x + be.x + xv.x;
    o.y = (v.y - mu) * inv * g.y + be.y + xv.y;
    o.z = (v.z - mu) * inv * g.z + be.z + xv.z;
    o.w = (v.w - mu) * inv * g.w + be.w + xv.w;
    *(float4*)&out[node * D + lane * 4] = o;
}

// ---------------------------------------------------------------------------
extern "C" void kernel_launch(void* const* d_in, const int* in_sizes, int n_in,
                              void* d_out, int out_size) {
    const float* x     = (const float*)d_in[0];
    const int*   ei    = (const int*)d_in[1];
    const float* W     = (const float*)d_in[2];
    const float* b     = (const float*)d_in[3];
    const float* gamma = (const float*)d_in[4];
    const float* beta  = (const float*)d_in[5];
    float*       out   = (float*)d_out;

    int n = in_sizes[0] / D;
    int E = in_sizes[1] / 2;
    int nb = (n + SCAN_ELEMS - 1) / SCAN_ELEMS;

    k_zero<<<(n + 255) / 256, 256>>>(n);
    k_count<<<(E + 255) / 256, 256>>>(ei, E);
    k_dis<<<(n + 255) / 256, 256>>>(n);

    int smem = SM_FLOATS * sizeof(float);  // ~136 KB
    cudaFuncSetAttribute(k_gemm, cudaFuncAttributeMaxDynamicSharedMemorySize, smem);
    k_gemm<<<(n + 127) / 128, 512, smem>>>(x, W, b, n);

    k_scan1<<<nb, 256>>>(n);
    k_scan2<<<1, SCAN_MAXBLK>>>(nb, n);
    k_scan3<<<nb, 256>>>(n);
    k_fill<<<(E + 255) / 256, 256>>>(ei, E);

    k_agg<<<(n + 7) / 8, 256>>>(x, gamma, beta, out, n);
}